// round 1
// baseline (speedup 1.0000x reference)
#include <cuda_runtime.h>

// Problem constants (fixed by the reference)
#define S_LEN   2048
#define NH      16
#define HD      64
#define E_DIM   1024
#define QKV_LD  3072          // 3*E
#define BATCH   2
#define M_TOTAL (BATCH * S_LEN)   // 4096

// Scratch (no cudaMalloc allowed): qkv projection output and attention output
__device__ float g_qkv [(size_t)M_TOTAL * QKV_LD];   // [B*S, 3E]
__device__ float g_vals[(size_t)M_TOTAL * E_DIM];    // [B*S, E]

// ---------------------------------------------------------------------------
// GEMM: C[m][n] = sum_k A[m][k] * W[n][k] + bias[n]
// A row-major [M,K], W row-major [N,K] (torch Linear weight layout).
// 128x128 block tile, BK=16, 256 threads, 8x8 per-thread micro-tile.
// M,N multiples of 128; K multiple of 16 (always true here).
// ---------------------------------------------------------------------------
__global__ __launch_bounds__(256) void gemm_nt_bias(
    const float* __restrict__ A, const float* __restrict__ W,
    const float* __restrict__ bias, float* __restrict__ C,
    int M, int N, int K)
{
    __shared__ float As[16][128];   // [k][m]
    __shared__ float Bs[16][128];   // [k][n]

    const int tid = threadIdx.x;
    const int m0  = blockIdx.y * 128;
    const int n0  = blockIdx.x * 128;
    const int tx  = tid & 15;
    const int ty  = tid >> 4;

    float acc[8][8];
#pragma unroll
    for (int i = 0; i < 8; i++)
#pragma unroll
        for (int j = 0; j < 8; j++) acc[i][j] = 0.f;

    for (int k0 = 0; k0 < K; k0 += 16) {
#pragma unroll
        for (int i = 0; i < 2; i++) {
            int idx = tid + i * 256;          // 0..511 float4 slots
            int r   = idx >> 2;               // 0..127
            int kc  = (idx & 3) * 4;          // 0,4,8,12
            float4 a = *(const float4*)(A + (size_t)(m0 + r) * K + k0 + kc);
            As[kc + 0][r] = a.x; As[kc + 1][r] = a.y;
            As[kc + 2][r] = a.z; As[kc + 3][r] = a.w;
            float4 b = *(const float4*)(W + (size_t)(n0 + r) * K + k0 + kc);
            Bs[kc + 0][r] = b.x; Bs[kc + 1][r] = b.y;
            Bs[kc + 2][r] = b.z; Bs[kc + 3][r] = b.w;
        }
        __syncthreads();
#pragma unroll
        for (int k = 0; k < 16; k++) {
            float4 a0 = *(const float4*)&As[k][ty * 8];
            float4 a1 = *(const float4*)&As[k][ty * 8 + 4];
            float4 b0 = *(const float4*)&Bs[k][tx * 8];
            float4 b1 = *(const float4*)&Bs[k][tx * 8 + 4];
            float af[8] = {a0.x, a0.y, a0.z, a0.w, a1.x, a1.y, a1.z, a1.w};
            float bf[8] = {b0.x, b0.y, b0.z, b0.w, b1.x, b1.y, b1.z, b1.w};
#pragma unroll
            for (int i = 0; i < 8; i++)
#pragma unroll
                for (int j = 0; j < 8; j++)
                    acc[i][j] += af[i] * bf[j];
        }
        __syncthreads();
    }

#pragma unroll
    for (int i = 0; i < 8; i++) {
        int m = m0 + ty * 8 + i;
#pragma unroll
        for (int j = 0; j < 8; j += 4) {
            int n = n0 + tx * 8 + j;
            float4 v;
            v.x = acc[i][j + 0] + bias[n + 0];
            v.y = acc[i][j + 1] + bias[n + 1];
            v.z = acc[i][j + 2] + bias[n + 2];
            v.w = acc[i][j + 3] + bias[n + 3];
            *(float4*)(C + (size_t)m * N + n) = v;
        }
    }
}

// ---------------------------------------------------------------------------
// Flash attention (fp32, online softmax).
// qkv layout: [B*S, 3E] where column index = h*192 + {0:q,64:k,128:v} + d.
// Block = (b*h, q-tile of 64 rows), 256 threads = 64 rows x 4 column-owners.
// Thread (row, tx) owns score columns j*4+tx (j=0..15) of each 64-wide KV tile
// and accumulates the FULL 64-dim O partial for its column subset in registers;
// the 4 owners merge via shfl-xor at the end.
// ---------------------------------------------------------------------------
#define ATT_LD 68   // padded row stride (floats) for conflict-free float4 LDS
#define ATT_SMEM_BYTES (3 * 64 * ATT_LD * 4)

__global__ __launch_bounds__(256) void flash_attn(
    const float* __restrict__ qkv, float* __restrict__ vals)
{
    extern __shared__ float smem[];
    float (*Qs)[ATT_LD] = (float(*)[ATT_LD])(smem);
    float (*Ks)[ATT_LD] = (float(*)[ATT_LD])(smem + 64 * ATT_LD);
    float (*Vs)[ATT_LD] = (float(*)[ATT_LD])(smem + 2 * 64 * ATT_LD);

    const int bh = blockIdx.x;             // 0..31
    const int qt = blockIdx.y;             // 0..31
    const int b  = bh >> 4;
    const int h  = bh & 15;
    const float* base = qkv + (size_t)b * S_LEN * QKV_LD + h * 192;

    const int tid = threadIdx.x;
    const int row = tid >> 2;              // 0..63
    const int tx  = tid & 3;

    // Load Q tile [64 x 64]
#pragma unroll
    for (int i = 0; i < 4; i++) {
        int idx = tid + i * 256;           // 0..1023 float4 slots
        int r   = idx >> 4;
        int c   = (idx & 15) * 4;
        *(float4*)&Qs[r][c] =
            *(const float4*)&base[(size_t)(qt * 64 + r) * QKV_LD + c];
    }

    float m = -1e30f, l = 0.f;
    float4 O[16];
#pragma unroll
    for (int i = 0; i < 16; i++) O[i] = make_float4(0.f, 0.f, 0.f, 0.f);

    for (int kt = 0; kt < S_LEN / 64; kt++) {
        __syncthreads();   // prior tile's reads done (and Qs ready on kt==0)
        // Load K,V tiles [64 x 64]
#pragma unroll
        for (int i = 0; i < 4; i++) {
            int idx = tid + i * 256;
            int r   = idx >> 4;
            int c   = (idx & 15) * 4;
            const float* rp = &base[(size_t)(kt * 64 + r) * QKV_LD];
            *(float4*)&Ks[r][c] = *(const float4*)&rp[64 + c];
            *(float4*)&Vs[r][c] = *(const float4*)&rp[128 + c];
        }
        __syncthreads();

        // Scores for this thread's 16 columns (jc = j*4 + tx)
        float s[16];
#pragma unroll
        for (int j = 0; j < 16; j++) s[j] = 0.f;
#pragma unroll
        for (int k4 = 0; k4 < 16; k4++) {
            float4 q = *(const float4*)&Qs[row][k4 * 4];
#pragma unroll
            for (int j = 0; j < 16; j++) {
                float4 kv = *(const float4*)&Ks[j * 4 + tx][k4 * 4];
                s[j] += q.x * kv.x + q.y * kv.y + q.z * kv.z + q.w * kv.w;
            }
        }

        // Online softmax (per-thread partial over its 16 columns)
        float mloc = m;
#pragma unroll
        for (int j = 0; j < 16; j++) {
            s[j] *= 0.125f;                // 1/sqrt(64)
            mloc = fmaxf(mloc, s[j]);
        }
        float corr = __expf(m - mloc);
        float lnew = l * corr;
#pragma unroll
        for (int j = 0; j < 16; j++) {
            s[j] = __expf(s[j] - mloc);
            lnew += s[j];
        }
        m = mloc; l = lnew;
#pragma unroll
        for (int i = 0; i < 16; i++) {
            O[i].x *= corr; O[i].y *= corr; O[i].z *= corr; O[i].w *= corr;
        }

        // O += P @ V over this thread's columns
#pragma unroll
        for (int j = 0; j < 16; j++) {
            const float p = s[j];
            const float* vrow = Vs[j * 4 + tx];
#pragma unroll
            for (int d4 = 0; d4 < 16; d4++) {
                float4 v = *(const float4*)&vrow[d4 * 4];
                O[d4].x += p * v.x; O[d4].y += p * v.y;
                O[d4].z += p * v.z; O[d4].w += p * v.w;
            }
        }
    }

    // Merge the 4 column-owners of each row (tx occupies lane bits [0:2))
#pragma unroll
    for (int st = 1; st <= 2; st <<= 1) {
        float om = __shfl_xor_sync(0xffffffffu, m, st);
        float ol = __shfl_xor_sync(0xffffffffu, l, st);
        float M2 = fmaxf(m, om);
        float c1 = __expf(m - M2);
        float c2 = __expf(om - M2);
        l = l * c1 + ol * c2;
#pragma unroll
        for (int i = 0; i < 16; i++) {
            float4 o = O[i];
            float rx = __shfl_xor_sync(0xffffffffu, o.x, st);
            float ry = __shfl_xor_sync(0xffffffffu, o.y, st);
            float rz = __shfl_xor_sync(0xffffffffu, o.z, st);
            float rw = __shfl_xor_sync(0xffffffffu, o.w, st);
            O[i].x = o.x * c1 + rx * c2;
            O[i].y = o.y * c1 + ry * c2;
            O[i].z = o.z * c1 + rz * c2;
            O[i].w = o.w * c1 + rw * c2;
        }
        m = M2;
    }

    // Write this thread's quarter of the row: d in [tx*16, tx*16+16)
    const float inv = 1.0f / l;
    const int qrow = qt * 64 + row;
    float* outp = vals + ((size_t)b * S_LEN + qrow) * E_DIM + h * HD + tx * 16;
#pragma unroll
    for (int q4 = 0; q4 < 4; q4++) {
        float4 o = O[tx * 4 + q4];
        o.x *= inv; o.y *= inv; o.z *= inv; o.w *= inv;
        *(float4*)&outp[q4 * 4] = o;
    }
}

// ---------------------------------------------------------------------------
extern "C" void kernel_launch(void* const* d_in, const int* in_sizes, int n_in,
                              void* d_out, int out_size)
{
    const float* x     = (const float*)d_in[0];
    const float* w_qkv = (const float*)d_in[1];
    const float* b_qkv = (const float*)d_in[2];
    const float* w_o   = (const float*)d_in[3];
    const float* b_o   = (const float*)d_in[4];
    float* out = (float*)d_out;

    float *qkv_p = nullptr, *vals_p = nullptr;
    cudaGetSymbolAddress((void**)&qkv_p,  g_qkv);
    cudaGetSymbolAddress((void**)&vals_p, g_vals);

    cudaFuncSetAttribute(flash_attn,
                         cudaFuncAttributeMaxDynamicSharedMemorySize,
                         ATT_SMEM_BYTES);

    // 1) QKV projection: [4096,1024] x [3072,1024]^T + b
    dim3 g1(QKV_LD / 128, M_TOTAL / 128);
    gemm_nt_bias<<<g1, 256>>>(x, w_qkv, b_qkv, qkv_p, M_TOTAL, QKV_LD, E_DIM);

    // 2) Attention
    dim3 ga(BATCH * NH, S_LEN / 64);
    flash_attn<<<ga, 256, ATT_SMEM_BYTES>>>(qkv_p, vals_p);

    // 3) Output projection: [4096,1024] x [1024,1024]^T + b
    dim3 g2(E_DIM / 128, M_TOTAL / 128);
    gemm_nt_bias<<<g2, 256>>>(vals_p, w_o, b_o, out, M_TOTAL, E_DIM, E_DIM);
}

// round 6
// speedup vs baseline: 4.9355x; 4.9355x over previous
#include <cuda_runtime.h>
#include <cstdint>

// Problem constants (fixed by the reference)
#define S_LEN   2048
#define NH      16
#define HD      64
#define E_DIM   1024
#define QKV_LD  3072          // 3*E
#define BATCH   2
#define M_TOTAL (BATCH * S_LEN)   // 4096

// Scratch (no cudaMalloc allowed)
__device__ float g_qkv [(size_t)M_TOTAL * QKV_LD];   // [B*S, 3E]
__device__ float g_vals[(size_t)M_TOTAL * E_DIM];    // [B*S, E]

// ---------------------------------------------------------------------------
// tf32 helpers (sm_80-era PTX only; no 'a'-arch features)
// ---------------------------------------------------------------------------
__device__ __forceinline__ uint32_t f2tf(float f) {
    uint32_t u;
    asm("cvt.rna.tf32.f32 %0, %1;" : "=r"(u) : "f"(f));
    return u;
}

// D(f32) += A(tf32) * B(tf32), m16n8k8, A row-major, B col-major
__device__ __forceinline__ void mma_tf32(float* d, const uint32_t* a, const uint32_t* b) {
    asm volatile(
        "mma.sync.aligned.m16n8k8.row.col.f32.tf32.tf32.f32 "
        "{%0,%1,%2,%3}, {%4,%5,%6,%7}, {%8,%9}, {%0,%1,%2,%3};\n"
        : "+f"(d[0]), "+f"(d[1]), "+f"(d[2]), "+f"(d[3])
        : "r"(a[0]), "r"(a[1]), "r"(a[2]), "r"(a[3]),
          "r"(b[0]), "r"(b[1]));
}

// ---------------------------------------------------------------------------
// GEMM: C[m][n] = sum_k A[m][k] * W[n][k] + bias[n]   (K = 1024 fixed)
// Block 128x256, BK=16, 256 threads = 8 warps (2m x 4n), warp tile 64x64.
// smem: A tile [128][20] (pad), W tile [256][20], tf32 values.
// ---------------------------------------------------------------------------
#define GPAD 20

__global__ __launch_bounds__(256) void gemm_mma_tf32(
    const float* __restrict__ A, const float* __restrict__ W,
    const float* __restrict__ bias, float* __restrict__ C, int N)
{
    __shared__ uint32_t As[128 * GPAD];   // 10240 B
    __shared__ uint32_t Ws[256 * GPAD];   // 20480 B

    const int tid  = threadIdx.x;
    const int lane = tid & 31;
    const int wid  = tid >> 5;
    const int wm   = wid >> 2;       // 0..1
    const int wn   = wid & 3;        // 0..3
    const int m0   = blockIdx.y * 128;
    const int n0   = blockIdx.x * 256;

    float acc[4][8][4];
#pragma unroll
    for (int mb = 0; mb < 4; mb++)
#pragma unroll
        for (int nb = 0; nb < 8; nb++)
#pragma unroll
            for (int j = 0; j < 4; j++) acc[mb][nb][j] = 0.f;

    // per-thread gmem load coords (BK=16 chunk)
    // A: 512 float4 -> 2/thread ; W: 1024 float4 -> 4/thread
    const int ar = tid >> 1;                 // 0..127  (2 threads per row)
    const int ac = (tid & 1) * 8;            // 0 or 8  (two float4 per row half)
    // actually use idx-based scheme: r = idx>>2, cq = idx&3
    float4 pa[2], pw[4];

    // prologue: load chunk 0
#pragma unroll
    for (int s = 0; s < 2; s++) {
        int idx = tid + s * 256;             // 0..511
        int r = idx >> 2, cq = idx & 3;
        pa[s] = *(const float4*)(A + (size_t)(m0 + r) * 1024 + 4 * cq);
    }
#pragma unroll
    for (int s = 0; s < 4; s++) {
        int idx = tid + s * 256;             // 0..1023
        int r = idx >> 2, cq = idx & 3;
        pw[s] = *(const float4*)(W + (size_t)(n0 + r) * 1024 + 4 * cq);
    }

    const int arow_base = (wm * 64 + (lane >> 2)) * GPAD + (lane & 3);
    const int wrow_base = (wn * 64 + (lane >> 2)) * GPAD + (lane & 3);
    (void)ar; (void)ac;

    for (int kc = 0; kc < 64; kc++) {
        // STS current chunk (tf32)
#pragma unroll
        for (int s = 0; s < 2; s++) {
            int idx = tid + s * 256;
            int r = idx >> 2, cq = idx & 3;
            uint4 v = { f2tf(pa[s].x), f2tf(pa[s].y), f2tf(pa[s].z), f2tf(pa[s].w) };
            *(uint4*)&As[r * GPAD + 4 * cq] = v;
        }
#pragma unroll
        for (int s = 0; s < 4; s++) {
            int idx = tid + s * 256;
            int r = idx >> 2, cq = idx & 3;
            uint4 v = { f2tf(pw[s].x), f2tf(pw[s].y), f2tf(pw[s].z), f2tf(pw[s].w) };
            *(uint4*)&Ws[r * GPAD + 4 * cq] = v;
        }
        __syncthreads();

        // prefetch next chunk while computing
        if (kc + 1 < 64) {
            const int k0 = (kc + 1) * 16;
#pragma unroll
            for (int s = 0; s < 2; s++) {
                int idx = tid + s * 256;
                int r = idx >> 2, cq = idx & 3;
                pa[s] = *(const float4*)(A + (size_t)(m0 + r) * 1024 + k0 + 4 * cq);
            }
#pragma unroll
            for (int s = 0; s < 4; s++) {
                int idx = tid + s * 256;
                int r = idx >> 2, cq = idx & 3;
                pw[s] = *(const float4*)(W + (size_t)(n0 + r) * 1024 + k0 + 4 * cq);
            }
        }

        // compute: 2 k8 sub-chunks
#pragma unroll
        for (int kc8 = 0; kc8 < 2; kc8++) {
            uint32_t af[4][4];
#pragma unroll
            for (int mb = 0; mb < 4; mb++) {
                const int base = arow_base + mb * 16 * GPAD + kc8 * 8;
                af[mb][0] = As[base];
                af[mb][1] = As[base + 8 * GPAD];
                af[mb][2] = As[base + 4];
                af[mb][3] = As[base + 8 * GPAD + 4];
            }
            uint32_t bf[8][2];
#pragma unroll
            for (int nb = 0; nb < 8; nb++) {
                const int base = wrow_base + nb * 8 * GPAD + kc8 * 8;
                bf[nb][0] = Ws[base];
                bf[nb][1] = Ws[base + 4];
            }
#pragma unroll
            for (int mb = 0; mb < 4; mb++)
#pragma unroll
                for (int nb = 0; nb < 8; nb++)
                    mma_tf32(acc[mb][nb], af[mb], bf[nb]);
        }
        __syncthreads();
    }

    // epilogue: bias + store
    float2 bv[8];
#pragma unroll
    for (int nb = 0; nb < 8; nb++) {
        int col = n0 + wn * 64 + nb * 8 + 2 * (lane & 3);
        bv[nb] = *(const float2*)&bias[col];
    }
#pragma unroll
    for (int mb = 0; mb < 4; mb++) {
        const int row = m0 + wm * 64 + mb * 16 + (lane >> 2);
#pragma unroll
        for (int nb = 0; nb < 8; nb++) {
            const int col = n0 + wn * 64 + nb * 8 + 2 * (lane & 3);
            float2 v0 = { acc[mb][nb][0] + bv[nb].x, acc[mb][nb][1] + bv[nb].y };
            float2 v1 = { acc[mb][nb][2] + bv[nb].x, acc[mb][nb][3] + bv[nb].y };
            *(float2*)(C + (size_t)row * N + col)        = v0;
            *(float2*)(C + (size_t)(row + 8) * N + col)  = v1;
        }
    }
}

// ---------------------------------------------------------------------------
// Flash attention with tf32 mma.sync.
// Block = (b,h) x q-tile(256 rows). 8 warps, warp owns 32 q-rows (2 m16 blocks).
// KV tiles of 64 keys. Online softmax on C-fragment layout; P goes through a
// per-warp smem buffer (warp-private, __syncwarp only) to re-enter PV as A.
// smem (uint32): Q[256][68], K[64][68], V[64][72], P[8 warps][32][68]
// ---------------------------------------------------------------------------
#define AQ_OFF 0
#define AK_OFF (256 * 68)                  // 17408
#define AV_OFF (AK_OFF + 64 * 68)          // 21760
#define AP_OFF (AV_OFF + 64 * 72)          // 26368
#define ATT_SMEM_U32 (AP_OFF + 8 * 32 * 68)  // 43776 u32 = 175104 B
#define ATT_SMEM_BYTES (ATT_SMEM_U32 * 4)

__global__ __launch_bounds__(256) void flash_attn_tc(
    const float* __restrict__ qkv, float* __restrict__ vals)
{
    extern __shared__ uint32_t sm[];
    uint32_t* Qs = sm + AQ_OFF;
    uint32_t* Ks = sm + AK_OFF;
    uint32_t* Vs = sm + AV_OFF;

    const int tid  = threadIdx.x;
    const int lane = tid & 31;
    const int wid  = tid >> 5;
    const int bh   = blockIdx.x;            // 0..31
    const int qt   = blockIdx.y;            // 0..7
    const int b    = bh >> 4;
    const int h    = bh & 15;
    const float* base = qkv + (size_t)b * S_LEN * QKV_LD + h * 192;

    uint32_t* Pw = sm + AP_OFF + wid * (32 * 68);

    // ---- load Q tile (256 x 64), scaled by 1/sqrt(64), tf32 ----
#pragma unroll
    for (int s = 0; s < 16; s++) {
        int idx = tid + s * 256;             // 0..4095
        int r = idx >> 4, cq = idx & 15;
        float4 v = *(const float4*)&base[(size_t)(qt * 256 + r) * QKV_LD + 4 * cq];
        uint4 u = { f2tf(v.x * 0.125f), f2tf(v.y * 0.125f),
                    f2tf(v.z * 0.125f), f2tf(v.w * 0.125f) };
        *(uint4*)&Qs[r * 68 + 4 * cq] = u;
    }

    float mrow[2][2], lrow[2][2];
    float oacc[2][8][4];
#pragma unroll
    for (int mb = 0; mb < 2; mb++)
#pragma unroll
        for (int hf = 0; hf < 2; hf++) { mrow[mb][hf] = -1e30f; lrow[mb][hf] = 0.f; }
#pragma unroll
    for (int mb = 0; mb < 2; mb++)
#pragma unroll
        for (int nb = 0; nb < 8; nb++)
#pragma unroll
            for (int j = 0; j < 4; j++) oacc[mb][nb][j] = 0.f;

    // per-thread frag base offsets
    const int qrow_base = (wid * 32 + (lane >> 2)) * 68 + (lane & 3);
    const int krow_base = (lane >> 2) * 68 + (lane & 3);
    const int vrow_base = (lane & 3) * 72 + (lane >> 2);
    const int prow_base = (lane >> 2) * 68 + (lane & 3);

    for (int kt = 0; kt < S_LEN / 64; kt++) {
        if (kt > 0) __syncthreads();     // all warps done reading K/V of prev tile
        // ---- load K,V tiles (64 x 64 each) ----
#pragma unroll
        for (int s = 0; s < 4; s++) {
            int idx = tid + s * 256;         // 0..1023
            int key = idx >> 4, cq = idx & 15;
            const float* rp = &base[(size_t)(kt * 64 + key) * QKV_LD];
            float4 kv = *(const float4*)&rp[64 + 4 * cq];
            float4 vv = *(const float4*)&rp[128 + 4 * cq];
            uint4 ku = { f2tf(kv.x), f2tf(kv.y), f2tf(kv.z), f2tf(kv.w) };
            uint4 vu = { f2tf(vv.x), f2tf(vv.y), f2tf(vv.z), f2tf(vv.w) };
            *(uint4*)&Ks[key * 68 + 4 * cq] = ku;
            *(uint4*)&Vs[key * 72 + 4 * cq] = vu;
        }
        __syncthreads();

        // ---- S = Q K^T (pre-scaled) ----
        float sacc[2][8][4];
#pragma unroll
        for (int mb = 0; mb < 2; mb++)
#pragma unroll
            for (int nb = 0; nb < 8; nb++)
#pragma unroll
                for (int j = 0; j < 4; j++) sacc[mb][nb][j] = 0.f;

#pragma unroll
        for (int kc8 = 0; kc8 < 8; kc8++) {
            uint32_t af[2][4];
#pragma unroll
            for (int mb = 0; mb < 2; mb++) {
                const int a0 = qrow_base + mb * 16 * 68 + kc8 * 8;
                af[mb][0] = Qs[a0];
                af[mb][1] = Qs[a0 + 8 * 68];
                af[mb][2] = Qs[a0 + 4];
                af[mb][3] = Qs[a0 + 8 * 68 + 4];
            }
            uint32_t bf[8][2];
#pragma unroll
            for (int nb = 0; nb < 8; nb++) {
                const int b0 = krow_base + nb * 8 * 68 + kc8 * 8;
                bf[nb][0] = Ks[b0];
                bf[nb][1] = Ks[b0 + 4];
            }
#pragma unroll
            for (int mb = 0; mb < 2; mb++)
#pragma unroll
                for (int nb = 0; nb < 8; nb++)
                    mma_tf32(sacc[mb][nb], af[mb], bf[nb]);
        }

        // ---- online softmax on fragment layout ----
        __syncwarp();   // P buffer of prev tile fully consumed (PV done)
#pragma unroll
        for (int mb = 0; mb < 2; mb++) {
#pragma unroll
            for (int hf = 0; hf < 2; hf++) {
                const int j0 = hf * 2;
                float tm = -1e30f;
#pragma unroll
                for (int nb = 0; nb < 8; nb++)
                    tm = fmaxf(tm, fmaxf(sacc[mb][nb][j0], sacc[mb][nb][j0 + 1]));
                tm = fmaxf(tm, __shfl_xor_sync(0xffffffffu, tm, 1));
                tm = fmaxf(tm, __shfl_xor_sync(0xffffffffu, tm, 2));
                const float mnew = fmaxf(mrow[mb][hf], tm);
                const float corr = __expf(mrow[mb][hf] - mnew);
                float ls = lrow[mb][hf] * corr;
                uint32_t* pr = Pw + (mb * 16 + hf * 8 + (lane >> 2)) * 68 + 2 * (lane & 3);
#pragma unroll
                for (int nb = 0; nb < 8; nb++) {
                    float p0 = __expf(sacc[mb][nb][j0]     - mnew);
                    float p1 = __expf(sacc[mb][nb][j0 + 1] - mnew);
                    ls += p0 + p1;
                    pr[nb * 8 + 0] = f2tf(p0);
                    pr[nb * 8 + 1] = f2tf(p1);
                    oacc[mb][nb][j0]     *= corr;
                    oacc[mb][nb][j0 + 1] *= corr;
                }
                mrow[mb][hf] = mnew;
                lrow[mb][hf] = ls;
            }
        }
        __syncwarp();

        // ---- O += P V ----
#pragma unroll
        for (int kc8 = 0; kc8 < 8; kc8++) {
            uint32_t af[2][4];
#pragma unroll
            for (int mb = 0; mb < 2; mb++) {
                const int a0 = prow_base + mb * 16 * 68 + kc8 * 8;
                af[mb][0] = Pw[a0];
                af[mb][1] = Pw[a0 + 8 * 68];
                af[mb][2] = Pw[a0 + 4];
                af[mb][3] = Pw[a0 + 8 * 68 + 4];
            }
            uint32_t bf[8][2];
#pragma unroll
            for (int nb = 0; nb < 8; nb++) {
                const int b0 = vrow_base + kc8 * 8 * 72 + nb * 8;
                bf[nb][0] = Vs[b0];
                bf[nb][1] = Vs[b0 + 4 * 72];
            }
#pragma unroll
            for (int mb = 0; mb < 2; mb++)
#pragma unroll
                for (int nb = 0; nb < 8; nb++)
                    mma_tf32(oacc[mb][nb], af[mb], bf[nb]);
        }
    }

    // ---- finalize: reduce l over 4-lane groups, normalize, store ----
#pragma unroll
    for (int mb = 0; mb < 2; mb++) {
        float inv[2];
#pragma unroll
        for (int hf = 0; hf < 2; hf++) {
            float l = lrow[mb][hf];
            l += __shfl_xor_sync(0xffffffffu, l, 1);
            l += __shfl_xor_sync(0xffffffffu, l, 2);
            inv[hf] = 1.0f / l;
        }
        const int row = qt * 256 + wid * 32 + mb * 16 + (lane >> 2);
        const int col = h * 64 + 2 * (lane & 3);
        float* o0 = vals + ((size_t)(b * S_LEN + row)) * E_DIM + col;
        float* o1 = vals + ((size_t)(b * S_LEN + row + 8)) * E_DIM + col;
#pragma unroll
        for (int nb = 0; nb < 8; nb++) {
            float2 v0 = { oacc[mb][nb][0] * inv[0], oacc[mb][nb][1] * inv[0] };
            float2 v1 = { oacc[mb][nb][2] * inv[1], oacc[mb][nb][3] * inv[1] };
            *(float2*)(o0 + nb * 8) = v0;
            *(float2*)(o1 + nb * 8) = v1;
        }
    }
}

// ---------------------------------------------------------------------------
extern "C" void kernel_launch(void* const* d_in, const int* in_sizes, int n_in,
                              void* d_out, int out_size)
{
    const float* x     = (const float*)d_in[0];
    const float* w_qkv = (const float*)d_in[1];
    const float* b_qkv = (const float*)d_in[2];
    const float* w_o   = (const float*)d_in[3];
    const float* b_o   = (const float*)d_in[4];
    float* out = (float*)d_out;

    float *qkv_p = nullptr, *vals_p = nullptr;
    cudaGetSymbolAddress((void**)&qkv_p,  g_qkv);
    cudaGetSymbolAddress((void**)&vals_p, g_vals);

    cudaFuncSetAttribute(flash_attn_tc,
                         cudaFuncAttributeMaxDynamicSharedMemorySize,
                         ATT_SMEM_BYTES);

    // 1) QKV projection: [4096,1024] x [3072,1024]^T + b
    dim3 g1(QKV_LD / 256, M_TOTAL / 128);     // (12, 32)
    gemm_mma_tf32<<<g1, 256>>>(x, w_qkv, b_qkv, qkv_p, QKV_LD);

    // 2) Attention (tensor-core flash)
    dim3 ga(BATCH * NH, S_LEN / 256);         // (32, 8)
    flash_attn_tc<<<ga, 256, ATT_SMEM_BYTES>>>(qkv_p, vals_p);

    // 3) Output projection: [4096,1024] x [1024,1024]^T + b
    dim3 g2(E_DIM / 256, M_TOTAL / 128);      // (4, 32)
    gemm_mma_tf32<<<g2, 256>>>(vals_p, w_o, b_o, out, E_DIM);
}

// round 7
// speedup vs baseline: 5.1895x; 1.0515x over previous
#include <cuda_runtime.h>
#include <cstdint>

// Problem constants (fixed by the reference)
#define S_LEN   2048
#define NH      16
#define HD      64
#define E_DIM   1024
#define QKV_LD  3072          // 3*E
#define BATCH   2
#define M_TOTAL (BATCH * S_LEN)   // 4096

// Scratch (no cudaMalloc allowed)
__device__ float g_qkv [(size_t)M_TOTAL * QKV_LD];   // [B*S, 3E]
__device__ float g_vals[(size_t)M_TOTAL * E_DIM];    // [B*S, E]

// ---------------------------------------------------------------------------
// tf32 helpers (sm_80-era PTX only)
// ---------------------------------------------------------------------------
__device__ __forceinline__ uint32_t f2tf(float f) {
    uint32_t u;
    asm("cvt.rna.tf32.f32 %0, %1;" : "=r"(u) : "f"(f));
    return u;
}

// D(f32) += A(tf32) * B(tf32), m16n8k8, A row-major, B col-major
__device__ __forceinline__ void mma_tf32(float* d, const uint32_t* a, const uint32_t* b) {
    asm volatile(
        "mma.sync.aligned.m16n8k8.row.col.f32.tf32.tf32.f32 "
        "{%0,%1,%2,%3}, {%4,%5,%6,%7}, {%8,%9}, {%0,%1,%2,%3};\n"
        : "+f"(d[0]), "+f"(d[1]), "+f"(d[2]), "+f"(d[3])
        : "r"(a[0]), "r"(a[1]), "r"(a[2]), "r"(a[3]),
          "r"(b[0]), "r"(b[1]));
}

// ---------------------------------------------------------------------------
// GEMM: C[m][n] = sum_k A[m][k] * W[n][k] + bias[n]   (K = 1024 fixed)
// Block 128x256, BK=16, 512 threads = 16 warps (4m x 4n), warp tile 32x64.
// Double-buffered smem (dynamic, 61440 B), one __syncthreads per k16.
// ---------------------------------------------------------------------------
#define GPAD 20
#define GA_SZ (128 * GPAD)    // 2560 u32 per buffer
#define GW_SZ (256 * GPAD)    // 5120 u32 per buffer
#define GEMM_SMEM_BYTES ((2 * GA_SZ + 2 * GW_SZ) * 4)   // 61440

__global__ __launch_bounds__(512, 1) void gemm_mma_tf32(
    const float* __restrict__ A, const float* __restrict__ W,
    const float* __restrict__ bias, float* __restrict__ C, int N)
{
    extern __shared__ uint32_t gsm[];
    uint32_t* AsB = gsm;                 // [2][GA_SZ]
    uint32_t* WsB = gsm + 2 * GA_SZ;     // [2][GW_SZ]

    const int tid  = threadIdx.x;
    const int lane = tid & 31;
    const int wid  = tid >> 5;
    const int wm   = wid >> 2;       // 0..3  (m: 32-row slabs)
    const int wn   = wid & 3;        // 0..3  (n: 64-col slabs)
    const int m0   = blockIdx.y * 128;
    const int n0   = blockIdx.x * 256;

    float acc[2][8][4];
#pragma unroll
    for (int mb = 0; mb < 2; mb++)
#pragma unroll
        for (int nb = 0; nb < 8; nb++)
#pragma unroll
            for (int j = 0; j < 4; j++) acc[mb][nb][j] = 0.f;

    // per-thread load coords: A chunk 128x16 = 512 float4 (1/thread),
    // W chunk 256x16 = 1024 float4 (2/thread)
    const int r_a  = tid >> 2;          // 0..127
    const int cq_a = tid & 3;           // float4 index in k16
    float4 pa, pw[2];

    // prologue: LDG chunk 0, STS buf 0
    pa = *(const float4*)(A + (size_t)(m0 + r_a) * 1024 + 4 * cq_a);
#pragma unroll
    for (int s = 0; s < 2; s++) {
        int idx = tid + s * 512;
        int r = idx >> 2, cq = idx & 3;
        pw[s] = *(const float4*)(W + (size_t)(n0 + r) * 1024 + 4 * cq);
    }
    {
        uint4 va = { f2tf(pa.x), f2tf(pa.y), f2tf(pa.z), f2tf(pa.w) };
        *(uint4*)&AsB[r_a * GPAD + 4 * cq_a] = va;
#pragma unroll
        for (int s = 0; s < 2; s++) {
            int idx = tid + s * 512;
            int r = idx >> 2, cq = idx & 3;
            uint4 v = { f2tf(pw[s].x), f2tf(pw[s].y), f2tf(pw[s].z), f2tf(pw[s].w) };
            *(uint4*)&WsB[r * GPAD + 4 * cq] = v;
        }
    }
    __syncthreads();

    const int arow_base = (wm * 32 + (lane >> 2)) * GPAD + (lane & 3);
    const int wrow_base = (wn * 64 + (lane >> 2)) * GPAD + (lane & 3);

    for (int kc = 0; kc < 64; kc++) {
        const int p = kc & 1;
        const bool pre = (kc + 1 < 64);

        // prefetch chunk kc+1 (overlaps compute below)
        if (pre) {
            const int k0 = (kc + 1) * 16;
            pa = *(const float4*)(A + (size_t)(m0 + r_a) * 1024 + k0 + 4 * cq_a);
#pragma unroll
            for (int s = 0; s < 2; s++) {
                int idx = tid + s * 512;
                int r = idx >> 2, cq = idx & 3;
                pw[s] = *(const float4*)(W + (size_t)(n0 + r) * 1024 + k0 + 4 * cq);
            }
        }

        // compute chunk kc from buffer p
        const uint32_t* As = AsB + p * GA_SZ;
        const uint32_t* Ws = WsB + p * GW_SZ;
#pragma unroll
        for (int kc8 = 0; kc8 < 2; kc8++) {
            uint32_t af[2][4];
#pragma unroll
            for (int mb = 0; mb < 2; mb++) {
                const int base = arow_base + mb * 16 * GPAD + kc8 * 8;
                af[mb][0] = As[base];
                af[mb][1] = As[base + 8 * GPAD];
                af[mb][2] = As[base + 4];
                af[mb][3] = As[base + 8 * GPAD + 4];
            }
            uint32_t bf[8][2];
#pragma unroll
            for (int nb = 0; nb < 8; nb++) {
                const int base = wrow_base + nb * 8 * GPAD + kc8 * 8;
                bf[nb][0] = Ws[base];
                bf[nb][1] = Ws[base + 4];
            }
#pragma unroll
            for (int mb = 0; mb < 2; mb++)
#pragma unroll
                for (int nb = 0; nb < 8; nb++)
                    mma_tf32(acc[mb][nb], af[mb], bf[nb]);
        }

        // store chunk kc+1 into the other buffer
        if (pre) {
            uint32_t* Asn = AsB + (p ^ 1) * GA_SZ;
            uint32_t* Wsn = WsB + (p ^ 1) * GW_SZ;
            uint4 va = { f2tf(pa.x), f2tf(pa.y), f2tf(pa.z), f2tf(pa.w) };
            *(uint4*)&Asn[r_a * GPAD + 4 * cq_a] = va;
#pragma unroll
            for (int s = 0; s < 2; s++) {
                int idx = tid + s * 512;
                int r = idx >> 2, cq = idx & 3;
                uint4 v = { f2tf(pw[s].x), f2tf(pw[s].y), f2tf(pw[s].z), f2tf(pw[s].w) };
                *(uint4*)&Wsn[r * GPAD + 4 * cq] = v;
            }
        }
        __syncthreads();
    }

    // epilogue: bias + store
    float2 bv[8];
#pragma unroll
    for (int nb = 0; nb < 8; nb++) {
        int col = n0 + wn * 64 + nb * 8 + 2 * (lane & 3);
        bv[nb] = *(const float2*)&bias[col];
    }
#pragma unroll
    for (int mb = 0; mb < 2; mb++) {
        const int row = m0 + wm * 32 + mb * 16 + (lane >> 2);
#pragma unroll
        for (int nb = 0; nb < 8; nb++) {
            const int col = n0 + wn * 64 + nb * 8 + 2 * (lane & 3);
            float2 v0 = { acc[mb][nb][0] + bv[nb].x, acc[mb][nb][1] + bv[nb].y };
            float2 v1 = { acc[mb][nb][2] + bv[nb].x, acc[mb][nb][3] + bv[nb].y };
            *(float2*)(C + (size_t)row * N + col)        = v0;
            *(float2*)(C + (size_t)(row + 8) * N + col)  = v1;
        }
    }
}

// ---------------------------------------------------------------------------
// Flash attention with tf32 mma.sync.
// Block = (b,h) x q-tile(128 rows). 8 warps, warp owns 16 q-rows (1 m16 block).
// KV tiles of 64 keys. Online softmax on C-fragment layout; P goes through a
// per-warp smem buffer (warp-private, __syncwarp only) to re-enter PV as A.
// smem (u32): Q[128][68], K[64][68], V[64][72], P[8][16][68] = 105472 B
// 2 CTAs/SM via __launch_bounds__(256, 2).
// ---------------------------------------------------------------------------
#define AQ_OFF 0
#define AK_OFF (128 * 68)                    // 8704
#define AV_OFF (AK_OFF + 64 * 68)            // 13056
#define AP_OFF (AV_OFF + 64 * 72)            // 17664
#define ATT_SMEM_U32 (AP_OFF + 8 * 16 * 68)  // 26368
#define ATT_SMEM_BYTES (ATT_SMEM_U32 * 4)    // 105472

__global__ __launch_bounds__(256, 2) void flash_attn_tc(
    const float* __restrict__ qkv, float* __restrict__ vals)
{
    extern __shared__ uint32_t sm[];
    uint32_t* Qs = sm + AQ_OFF;
    uint32_t* Ks = sm + AK_OFF;
    uint32_t* Vs = sm + AV_OFF;

    const int tid  = threadIdx.x;
    const int lane = tid & 31;
    const int wid  = tid >> 5;
    const int bh   = blockIdx.x;            // 0..31
    const int qt   = blockIdx.y;            // 0..15
    const int b    = bh >> 4;
    const int h    = bh & 15;
    const float* base = qkv + (size_t)b * S_LEN * QKV_LD + h * 192;

    uint32_t* Pw = sm + AP_OFF + wid * (16 * 68);

    // ---- load Q tile (128 x 64), scaled by 1/sqrt(64), tf32 ----
#pragma unroll
    for (int s = 0; s < 8; s++) {
        int idx = tid + s * 256;             // 0..2047
        int r = idx >> 4, cq = idx & 15;
        float4 v = *(const float4*)&base[(size_t)(qt * 128 + r) * QKV_LD + 4 * cq];
        uint4 u = { f2tf(v.x * 0.125f), f2tf(v.y * 0.125f),
                    f2tf(v.z * 0.125f), f2tf(v.w * 0.125f) };
        *(uint4*)&Qs[r * 68 + 4 * cq] = u;
    }

    float mrow[2], lrow[2];
    float oacc[8][4];
#pragma unroll
    for (int hf = 0; hf < 2; hf++) { mrow[hf] = -1e30f; lrow[hf] = 0.f; }
#pragma unroll
    for (int nb = 0; nb < 8; nb++)
#pragma unroll
        for (int j = 0; j < 4; j++) oacc[nb][j] = 0.f;

    const int qrow_base = (wid * 16 + (lane >> 2)) * 68 + (lane & 3);
    const int krow_base = (lane >> 2) * 68 + (lane & 3);
    const int vrow_base = (lane & 3) * 72 + (lane >> 2);
    const int prow_base = (lane >> 2) * 68 + (lane & 3);

    for (int kt = 0; kt < S_LEN / 64; kt++) {
        if (kt > 0) __syncthreads();     // all warps done with prev K/V
        // ---- load K,V tiles (64 x 64 each) ----
#pragma unroll
        for (int s = 0; s < 4; s++) {
            int idx = tid + s * 256;         // 0..1023
            int key = idx >> 4, cq = idx & 15;
            const float* rp = &base[(size_t)(kt * 64 + key) * QKV_LD];
            float4 kv = *(const float4*)&rp[64 + 4 * cq];
            float4 vv = *(const float4*)&rp[128 + 4 * cq];
            uint4 ku = { f2tf(kv.x), f2tf(kv.y), f2tf(kv.z), f2tf(kv.w) };
            uint4 vu = { f2tf(vv.x), f2tf(vv.y), f2tf(vv.z), f2tf(vv.w) };
            *(uint4*)&Ks[key * 68 + 4 * cq] = ku;
            *(uint4*)&Vs[key * 72 + 4 * cq] = vu;
        }
        __syncthreads();

        // ---- S = Q K^T (pre-scaled) ----
        float sacc[8][4];
#pragma unroll
        for (int nb = 0; nb < 8; nb++)
#pragma unroll
            for (int j = 0; j < 4; j++) sacc[nb][j] = 0.f;

#pragma unroll
        for (int kc8 = 0; kc8 < 8; kc8++) {
            uint32_t af[4];
            {
                const int a0 = qrow_base + kc8 * 8;
                af[0] = Qs[a0];
                af[1] = Qs[a0 + 8 * 68];
                af[2] = Qs[a0 + 4];
                af[3] = Qs[a0 + 8 * 68 + 4];
            }
            uint32_t bf[8][2];
#pragma unroll
            for (int nb = 0; nb < 8; nb++) {
                const int b0 = krow_base + nb * 8 * 68 + kc8 * 8;
                bf[nb][0] = Ks[b0];
                bf[nb][1] = Ks[b0 + 4];
            }
#pragma unroll
            for (int nb = 0; nb < 8; nb++)
                mma_tf32(sacc[nb], af, bf[nb]);
        }

        // ---- online softmax on fragment layout ----
        __syncwarp();   // P buffer of prev tile fully consumed
#pragma unroll
        for (int hf = 0; hf < 2; hf++) {
            const int j0 = hf * 2;
            float tm = -1e30f;
#pragma unroll
            for (int nb = 0; nb < 8; nb++)
                tm = fmaxf(tm, fmaxf(sacc[nb][j0], sacc[nb][j0 + 1]));
            tm = fmaxf(tm, __shfl_xor_sync(0xffffffffu, tm, 1));
            tm = fmaxf(tm, __shfl_xor_sync(0xffffffffu, tm, 2));
            const float mnew = fmaxf(mrow[hf], tm);
            const float corr = __expf(mrow[hf] - mnew);
            float ls = lrow[hf] * corr;
            uint32_t* pr = Pw + (hf * 8 + (lane >> 2)) * 68 + 2 * (lane & 3);
#pragma unroll
            for (int nb = 0; nb < 8; nb++) {
                float p0 = __expf(sacc[nb][j0]     - mnew);
                float p1 = __expf(sacc[nb][j0 + 1] - mnew);
                ls += p0 + p1;
                pr[nb * 8 + 0] = f2tf(p0);
                pr[nb * 8 + 1] = f2tf(p1);
                oacc[nb][j0]     *= corr;
                oacc[nb][j0 + 1] *= corr;
            }
            mrow[hf] = mnew;
            lrow[hf] = ls;
        }
        __syncwarp();

        // ---- O += P V ----
#pragma unroll
        for (int kc8 = 0; kc8 < 8; kc8++) {
            uint32_t af[4];
            {
                const int a0 = prow_base + kc8 * 8;
                af[0] = Pw[a0];
                af[1] = Pw[a0 + 8 * 68];
                af[2] = Pw[a0 + 4];
                af[3] = Pw[a0 + 8 * 68 + 4];
            }
            uint32_t bf[8][2];
#pragma unroll
            for (int nb = 0; nb < 8; nb++) {
                const int b0 = vrow_base + kc8 * 8 * 72 + nb * 8;
                bf[nb][0] = Vs[b0];
                bf[nb][1] = Vs[b0 + 4 * 72];
            }
#pragma unroll
            for (int nb = 0; nb < 8; nb++)
                mma_tf32(oacc[nb], af, bf[nb]);
        }
    }

    // ---- finalize: reduce l over 4-lane groups, normalize, store ----
    float inv[2];
#pragma unroll
    for (int hf = 0; hf < 2; hf++) {
        float l = lrow[hf];
        l += __shfl_xor_sync(0xffffffffu, l, 1);
        l += __shfl_xor_sync(0xffffffffu, l, 2);
        inv[hf] = 1.0f / l;
    }
    const int row = qt * 128 + wid * 16 + (lane >> 2);
    const int col = h * 64 + 2 * (lane & 3);
    float* o0 = vals + ((size_t)(b * S_LEN + row)) * E_DIM + col;
    float* o1 = vals + ((size_t)(b * S_LEN + row + 8)) * E_DIM + col;
#pragma unroll
    for (int nb = 0; nb < 8; nb++) {
        float2 v0 = { oacc[nb][0] * inv[0], oacc[nb][1] * inv[0] };
        float2 v1 = { oacc[nb][2] * inv[1], oacc[nb][3] * inv[1] };
        *(float2*)(o0 + nb * 8) = v0;
        *(float2*)(o1 + nb * 8) = v1;
    }
}

// ---------------------------------------------------------------------------
extern "C" void kernel_launch(void* const* d_in, const int* in_sizes, int n_in,
                              void* d_out, int out_size)
{
    const float* x     = (const float*)d_in[0];
    const float* w_qkv = (const float*)d_in[1];
    const float* b_qkv = (const float*)d_in[2];
    const float* w_o   = (const float*)d_in[3];
    const float* b_o   = (const float*)d_in[4];
    float* out = (float*)d_out;

    float *qkv_p = nullptr, *vals_p = nullptr;
    cudaGetSymbolAddress((void**)&qkv_p,  g_qkv);
    cudaGetSymbolAddress((void**)&vals_p, g_vals);

    cudaFuncSetAttribute(gemm_mma_tf32,
                         cudaFuncAttributeMaxDynamicSharedMemorySize,
                         GEMM_SMEM_BYTES);
    cudaFuncSetAttribute(flash_attn_tc,
                         cudaFuncAttributeMaxDynamicSharedMemorySize,
                         ATT_SMEM_BYTES);

    // 1) QKV projection: [4096,1024] x [3072,1024]^T + b
    dim3 g1(QKV_LD / 256, M_TOTAL / 128);     // (12, 32)
    gemm_mma_tf32<<<g1, 512, GEMM_SMEM_BYTES>>>(x, w_qkv, b_qkv, qkv_p, QKV_LD);

    // 2) Attention (tensor-core flash)
    dim3 ga(BATCH * NH, S_LEN / 128);         // (32, 16)
    flash_attn_tc<<<ga, 256, ATT_SMEM_BYTES>>>(qkv_p, vals_p);

    // 3) Output projection: [4096,1024] x [1024,1024]^T + b
    dim3 g2(E_DIM / 256, M_TOTAL / 128);      // (4, 32)
    gemm_mma_tf32<<<g2, 512, GEMM_SMEM_BYTES>>>(vals_p, w_o, b_o, out, E_DIM);
}